// round 14
// baseline (speedup 1.0000x reference)
#include <cuda_runtime.h>
#include <cuda_fp16.h>
#include <math.h>
#include <stdint.h>

// ---------------------------------------------------------------------------
// Problem constants
// ---------------------------------------------------------------------------
#define B_SZ 16
#define T_SZ 1024
#define D_SZ 1024
#define E_SZ 64
#define TS   (T_SZ - 1)          // 1023
#define M_ROWS (TS * B_SZ)       // 16368
#define M_PAD  16384
#define K1 2048
#define N1 4096
#define K2 4096
#define N2 1024
#define K3 1024
#define N3 64
#define LOGITS_ELEMS (M_ROWS * E_SZ)

// Big-GEMM tiling: block 128x128, 4 warps (2x2), warp tile 64x64, BK=32
#define BM 128
#define BN 128
#define BK 32
#define STAGES 4
#define ROW_BYTES 80             // 64B data + 16B skew
#define ARR_BYTES (BM * ROW_BYTES)          // 10240
#define STAGE_BYTES (2 * ARR_BYTES)         // 20480
#define SMEM_TOTAL (STAGES * STAGE_BYTES)   // 81920

// GEMM3 tiling (256 threads, 8 warps 4x2, warp tile 32x32)
#define G3_ROW 80
#define G3_A_BYTES (BM * G3_ROW)
#define G3_B_BYTES (64 * G3_ROW)
#define G3_STAGE (G3_A_BYTES + G3_B_BYTES)
#define G3_SMEM (4 * G3_STAGE)

// ---------------------------------------------------------------------------
// Device scratch
// ---------------------------------------------------------------------------
__device__ __align__(16) __half g_a1[(size_t)M_PAD * K1];
__device__ __align__(16) __half g_w1[(size_t)N1 * K1];
__device__ __align__(16) __half g_hid[(size_t)M_PAD * N1];
__device__ __align__(16) __half g_w2[(size_t)N2 * K2];
__device__ __align__(16) __half g_xh16[(size_t)M_PAD * N2];
__device__ __align__(16) __half g_wpi[(size_t)N3 * K3];
__device__ __align__(16) float  g_bpi[N3];

// ---------------------------------------------------------------------------
// PTX helpers
// ---------------------------------------------------------------------------
__device__ __forceinline__ uint32_t smem_u32(const void* p) {
    uint32_t a;
    asm("{ .reg .u64 t; cvta.to.shared.u64 t, %1; cvt.u32.u64 %0, t; }" : "=r"(a) : "l"(p));
    return a;
}
__device__ __forceinline__ void cp_async16(uint32_t dst, const void* src) {
    asm volatile("cp.async.cg.shared.global [%0], [%1], 16;" :: "r"(dst), "l"(src));
}
__device__ __forceinline__ void cp_commit() {
    asm volatile("cp.async.commit_group;" ::: "memory");
}
template <int N>
__device__ __forceinline__ void cp_wait() {
    asm volatile("cp.async.wait_group %0;" :: "n"(N) : "memory");
}
__device__ __forceinline__ void ldsm_x4(uint32_t* r, uint32_t addr) {
    asm volatile("ldmatrix.sync.aligned.m8n8.x4.shared.b16 {%0,%1,%2,%3}, [%4];"
                 : "=r"(r[0]), "=r"(r[1]), "=r"(r[2]), "=r"(r[3]) : "r"(addr));
}
__device__ __forceinline__ void mma_f16(float* d, const uint32_t* a, uint32_t b0, uint32_t b1) {
    asm volatile(
        "mma.sync.aligned.m16n8k16.row.col.f32.f16.f16.f32 "
        "{%0,%1,%2,%3}, {%4,%5,%6,%7}, {%8,%9}, {%0,%1,%2,%3};"
        : "+f"(d[0]), "+f"(d[1]), "+f"(d[2]), "+f"(d[3])
        : "r"(a[0]), "r"(a[1]), "r"(a[2]), "r"(a[3]), "r"(b0), "r"(b1));
}
__device__ __forceinline__ ushort4 cvt4(float4 v) {
    return make_ushort4(
        __half_as_ushort(__float2half_rn(v.x)), __half_as_ushort(__float2half_rn(v.y)),
        __half_as_ushort(__float2half_rn(v.z)), __half_as_ushort(__float2half_rn(v.w)));
}

// ---------------------------------------------------------------------------
// Merged prep
// ---------------------------------------------------------------------------
#define R1 (N1 * K1 / 4)
#define R2 (N2 * K2 / 4)
#define R3 (N3 * K3 / 4)
#define RPAD ((M_PAD - M_ROWS) * K1 / 8)
#define RTOT (R1 + R2 + R3 + RPAD + N3)

__global__ void prep_kernel(const float* __restrict__ p1_w, const float* __restrict__ p2_w,
                            const float* __restrict__ W_w, const float* __restrict__ pi,
                            const float* __restrict__ Wb,
                            __half* __restrict__ w1, __half* __restrict__ w2,
                            __half* __restrict__ wpi, float* __restrict__ bpi,
                            __half* __restrict__ a1) {
    int i = blockIdx.x * blockDim.x + threadIdx.x;
    if (i < R1) {
        ((ushort4*)w1)[i] = cvt4(((const float4*)p1_w)[i]);
    } else if (i < R1 + R2) {
        int j = i - R1;
        ((ushort4*)w2)[j] = cvt4(((const float4*)p2_w)[j]);
    } else if (i < R1 + R2 + R3) {
        int j = i - R1 - R2;
        float4 v = ((const float4*)W_w)[j];
        float p = pi[j >> 8];
        v.x *= p; v.y *= p; v.z *= p; v.w *= p;
        ((ushort4*)wpi)[j] = cvt4(v);
    } else if (i < R1 + R2 + R3 + RPAD) {
        int j = i - R1 - R2 - R3;
        ((uint4*)(a1 + (size_t)M_ROWS * K1))[j] = make_uint4(0, 0, 0, 0);
    } else if (i < RTOT) {
        int j = i - R1 - R2 - R3 - RPAD;
        bpi[j] = Wb[j] * pi[j];
    }
}

// ---------------------------------------------------------------------------
// Fused EMA (chunked parallel scan) + x-half conversion
// ---------------------------------------------------------------------------
__global__ void __launch_bounds__(256)
ema_fused_kernel(const float* __restrict__ seq, const float* __restrict__ beta_raw,
                 __half* __restrict__ a1) {
    __shared__ float sL[16][16];
    __shared__ float sBP[16][16];
    const int tid = threadIdx.x;
    const int dl = tid & 15;
    const int c = tid >> 4;
    const int b = blockIdx.x >> 6;
    const int d = ((blockIdx.x & 63) << 4) + dl;
    const float beta = 1.0f / (1.0f + expf(-beta_raw[d]));
    const int t0 = c * 64;
    const int t1 = (t0 + 64 < TS) ? t0 + 64 : TS;
    const float* sp = seq + (size_t)b * T_SZ * D_SZ + d;

    float L = 0.0f, bp = 1.0f;
#pragma unroll 4
    for (int t = t0; t < t1; ++t) {
        L = fmaf(beta, L, sp[(size_t)t * D_SZ]);
        bp *= beta;
    }
    sL[c][dl] = L;
    sBP[c][dl] = bp;
    __syncthreads();

    float H = 0.0f;
    for (int j = 0; j < c; ++j)
        H = fmaf(sBP[j][dl], H, sL[j][dl]);

    float h = H;
#pragma unroll 4
    for (int t = t0; t < t1; ++t) {
        float x = sp[(size_t)t * D_SZ];
        h = fmaf(beta, h, x);
        const size_t m = (size_t)t * B_SZ + b;
        a1[m * K1 + d] = __float2half_rn(x);
        a1[m * K1 + D_SZ + d] = __float2half_rn(h);
    }
}

// ---------------------------------------------------------------------------
// fp16 mma.sync GEMM, fp32 acc, warp tile 64x64, 128 threads (4 warps 2x2),
// BK=32, 4-stage cp.async + register double-buffered fragments (R11 form),
// with half of the second MMA block issued BEFORE the chunk barrier so the
// tensor pipe drains during barrier-arrival skew.
// EPI 1: relu(acc+bias) -> fp16 outH
// EPI 2: acc+bias -> fp16 outH (all rows) + fp32 outF (m<M_ROWS)
// ---------------------------------------------------------------------------
template <int EPI>
__global__ void __launch_bounds__(128, 2)
gemm_f16(const __half* __restrict__ A, const __half* __restrict__ Wh,
         const float* __restrict__ bias,
         __half* __restrict__ outH, float* __restrict__ outF, int N, int K) {
    extern __shared__ char smem[];
    const uint32_t sbase = smem_u32(smem);
    const int tid = threadIdx.x;
    const int lane = tid & 31;
    const int wid = tid >> 5;            // 0..3
    const int wm0 = (wid & 1) * 64;
    const int wn0 = (wid >> 1) * 64;
    const int m0 = blockIdx.y * BM;
    const int n0 = blockIdx.x * BN;
    const int NK = K / BK;

    float acc[4][8][4];
#pragma unroll
    for (int a = 0; a < 4; ++a)
#pragma unroll
        for (int b = 0; b < 8; ++b)
#pragma unroll
            for (int c = 0; c < 4; ++c) acc[a][b][c] = 0.0f;

    // double-buffered fragments
    uint32_t ah[2][4][4], bh[2][4][4];

    auto load_stage = [&](int kc) {
        const uint32_t sb = sbase + (uint32_t)(kc % STAGES) * STAGE_BYTES;
        const size_t gcol = (size_t)kc * BK;
#pragma unroll
        for (int q = 0; q < 4; ++q) {
            const int s = tid + q * 128;
            const int r = s >> 2, ch = s & 3;
            const uint32_t so = (uint32_t)(r * ROW_BYTES + ch * 16);
            cp_async16(sb + so, A + (size_t)(m0 + r) * K + gcol + ch * 8);
            cp_async16(sb + ARR_BYTES + so, Wh + (size_t)(n0 + r) * K + gcol + ch * 8);
        }
        cp_commit();
    };

    const uint32_t lrow = (uint32_t)(lane & 15);
    const uint32_t lcol = (uint32_t)((lane >> 4) * 16);

    auto ldsm_frags = [&](int kc, int j, uint32_t (*A4)[4], uint32_t (*B4)[4]) {
        const uint32_t sb = sbase + (uint32_t)(kc % STAGES) * STAGE_BYTES;
        const uint32_t colb = (uint32_t)(j * 32) + lcol;
#pragma unroll
        for (int mf = 0; mf < 4; ++mf)
            ldsm_x4(A4[mf], sb + (uint32_t)((wm0 + mf * 16 + lrow) * ROW_BYTES) + colb);
#pragma unroll
        for (int np = 0; np < 4; ++np)
            ldsm_x4(B4[np], sb + ARR_BYTES +
                            (uint32_t)((wn0 + np * 16 + lrow) * ROW_BYTES) + colb);
    };

    auto mma_all = [&](uint32_t (*A4)[4], uint32_t (*B4)[4]) {
#pragma unroll
        for (int mf = 0; mf < 4; ++mf) {
#pragma unroll
            for (int np = 0; np < 4; ++np) {
                mma_f16(acc[mf][2 * np],     A4[mf], B4[np][0], B4[np][2]);
                mma_f16(acc[mf][2 * np + 1], A4[mf], B4[np][1], B4[np][3]);
            }
        }
    };

    // half = 0 -> mf 0,1 ; half = 1 -> mf 2,3   (16 MMAs each)
    auto mma_half = [&](uint32_t (*A4)[4], uint32_t (*B4)[4], int half) {
#pragma unroll
        for (int mi = 0; mi < 2; ++mi) {
            const int mf = half * 2 + mi;
#pragma unroll
            for (int np = 0; np < 4; ++np) {
                mma_f16(acc[mf][2 * np],     A4[mf], B4[np][0], B4[np][2]);
                mma_f16(acc[mf][2 * np + 1], A4[mf], B4[np][1], B4[np][3]);
            }
        }
    };

    // Prologue: 3 stages in flight; stage 0 resident; frags (0, j0) loaded.
    load_stage(0);
    load_stage(1);
    load_stage(2);
    cp_wait<2>();
    __syncthreads();
    ldsm_frags(0, 0, ah[0], bh[0]);

    for (int kc = 0; kc < NK; ++kc) {
        // j = 0: prefetch frags (kc, j1) into buf1, compute buf0
        ldsm_frags(kc, 1, ah[1], bh[1]);
        mma_all(ah[0], bh[0]);

        // first half of buf1 MMAs BEFORE the barrier: drains during arrival skew
        mma_half(ah[1], bh[1], 0);

        // j = 1: advance stage pipeline, prefetch frags (kc+1, j0) into buf0
        if (kc + 1 < NK) {
            if (kc + 3 < NK) {
                load_stage(kc + 3);   // safe: all reads of this slot precede barrier kc-1
                cp_wait<2>();         // retires group kc+1 (stage kc+1 resident)
            } else if (kc + 2 < NK) {
                cp_wait<1>();
            } else {
                cp_wait<0>();
            }
            __syncthreads();
            ldsm_frags(kc + 1, 0, ah[0], bh[0]);
        }
        mma_half(ah[1], bh[1], 1);
    }

    // Epilogue
    const int g = lane >> 2;
    const int t2 = (lane & 3) * 2;
#pragma unroll
    for (int mf = 0; mf < 4; ++mf) {
#pragma unroll
        for (int nf = 0; nf < 8; ++nf) {
            const int n = n0 + wn0 + nf * 8 + t2;
            const float2 bv = *(const float2*)(bias + n);
#pragma unroll
            for (int h = 0; h < 2; ++h) {
                const int m = m0 + wm0 + mf * 16 + g + h * 8;
                float v0 = acc[mf][nf][h * 2 + 0] + bv.x;
                float v1 = acc[mf][nf][h * 2 + 1] + bv.y;
                if (EPI == 1) {
                    v0 = fmaxf(v0, 0.0f);
                    v1 = fmaxf(v1, 0.0f);
                    *(ushort2*)(outH + (size_t)m * N + n) =
                        make_ushort2(__half_as_ushort(__float2half_rn(v0)),
                                     __half_as_ushort(__float2half_rn(v1)));
                } else {
                    *(ushort2*)(outH + (size_t)m * N + n) =
                        make_ushort2(__half_as_ushort(__float2half_rn(v0)),
                                     __half_as_ushort(__float2half_rn(v1)));
                    if (m < M_ROWS)
                        *(float2*)(outF + (size_t)m * N + n) = make_float2(v0, v1);
                }
            }
        }
    }
}

// ---------------------------------------------------------------------------
// GEMM3 (mma fp16): logits = xh16 @ Wpi^T + bpi   (BK=32, 4 stages)
// ---------------------------------------------------------------------------
__global__ void __launch_bounds__(256, 1)
gemm3_mma(const __half* __restrict__ A, const __half* __restrict__ Wpi,
          const float* __restrict__ bpi, float* __restrict__ C) {
    const int K = K3;
    extern __shared__ char smem[];
    const uint32_t sbase = smem_u32(smem);
    const int tid = threadIdx.x;
    const int lane = tid & 31;
    const int wid = tid >> 5;
    const int wm0 = (wid & 3) * 32;
    const int wn0 = (wid >> 2) * 32;
    const int m0 = blockIdx.x * BM;
    const int NK = K / 32;

    float acc[2][4][4];
#pragma unroll
    for (int a = 0; a < 2; ++a)
#pragma unroll
        for (int b = 0; b < 4; ++b)
#pragma unroll
            for (int c = 0; c < 4; ++c) acc[a][b][c] = 0.0f;

    auto load_stage = [&](int kc) {
        const uint32_t sb = sbase + (uint32_t)(kc % 4) * G3_STAGE;
        const size_t gcol = (size_t)kc * 32;
#pragma unroll
        for (int q = 0; q < 2; ++q) {
            const int s = tid + q * 256;
            const int r = s >> 2, ch = s & 3;
            cp_async16(sb + (uint32_t)(r * G3_ROW + ch * 16),
                       A + (size_t)(m0 + r) * K + gcol + ch * 8);
        }
        {
            const int r = tid >> 2, ch = tid & 3;
            cp_async16(sb + G3_A_BYTES + (uint32_t)(r * G3_ROW + ch * 16),
                       Wpi + (size_t)r * K + gcol + ch * 8);
        }
        cp_commit();
    };

    load_stage(0);
    load_stage(1);
    load_stage(2);

    const uint32_t lrow = (uint32_t)(lane & 15);
    const uint32_t lcol = (uint32_t)((lane >> 4) * 16);

    for (int kc = 0; kc < NK; ++kc) {
        const int rem = NK - 1 - kc;
        if (rem >= 2) cp_wait<2>();
        else if (rem == 1) cp_wait<1>();
        else cp_wait<0>();
        __syncthreads();
        if (kc + 3 < NK) load_stage(kc + 3);

        const uint32_t sb = sbase + (uint32_t)(kc % 4) * G3_STAGE;
#pragma unroll
        for (int j = 0; j < 2; ++j) {
            const uint32_t colb = (uint32_t)(j * 32) + lcol;
            uint32_t ah[2][4];
#pragma unroll
            for (int mf = 0; mf < 2; ++mf)
                ldsm_x4(ah[mf], sb + (uint32_t)((wm0 + mf * 16 + lrow) * G3_ROW) + colb);
            uint32_t bh[2][4];
#pragma unroll
            for (int np = 0; np < 2; ++np)
                ldsm_x4(bh[np], sb + G3_A_BYTES +
                                (uint32_t)((wn0 + np * 16 + lrow) * G3_ROW) + colb);
#pragma unroll
            for (int mf = 0; mf < 2; ++mf) {
#pragma unroll
                for (int np = 0; np < 2; ++np) {
                    mma_f16(acc[mf][2 * np],     ah[mf], bh[np][0], bh[np][2]);
                    mma_f16(acc[mf][2 * np + 1], ah[mf], bh[np][1], bh[np][3]);
                }
            }
        }
    }

    const int g = lane >> 2;
    const int t2 = (lane & 3) * 2;
#pragma unroll
    for (int mf = 0; mf < 2; ++mf) {
#pragma unroll
        for (int nf = 0; nf < 4; ++nf) {
            const int n = wn0 + nf * 8 + t2;
            const float2 bv = *(const float2*)(bpi + n);
#pragma unroll
            for (int h = 0; h < 2; ++h) {
                const int m = m0 + wm0 + mf * 16 + g + h * 8;
                if (m < M_ROWS) {
                    float v0 = acc[mf][nf][h * 2 + 0] + bv.x;
                    float v1 = acc[mf][nf][h * 2 + 1] + bv.y;
                    *(float2*)(C + (size_t)m * N3 + n) = make_float2(v0, v1);
                }
            }
        }
    }
}

// ---------------------------------------------------------------------------
// Launch
// ---------------------------------------------------------------------------
extern "C" void kernel_launch(void* const* d_in, const int* in_sizes, int n_in,
                              void* d_out, int out_size) {
    const float* seq      = (const float*)d_in[0];
    const float* pi       = (const float*)d_in[1];
    const float* beta_raw = (const float*)d_in[2];
    const float* p1_w     = (const float*)d_in[3];
    const float* p1_b     = (const float*)d_in[4];
    const float* p2_w     = (const float*)d_in[5];
    const float* p2_b     = (const float*)d_in[6];
    const float* W_w      = (const float*)d_in[7];
    const float* W_b      = (const float*)d_in[8];

    float* logits = (float*)d_out;
    float* xhat   = (float*)d_out + LOGITS_ELEMS;

    __half *a1, *w1, *hid, *w2, *xh16, *wpi;
    float* bpi;
    cudaGetSymbolAddress((void**)&a1, g_a1);
    cudaGetSymbolAddress((void**)&w1, g_w1);
    cudaGetSymbolAddress((void**)&hid, g_hid);
    cudaGetSymbolAddress((void**)&w2, g_w2);
    cudaGetSymbolAddress((void**)&xh16, g_xh16);
    cudaGetSymbolAddress((void**)&wpi, g_wpi);
    cudaGetSymbolAddress((void**)&bpi, g_bpi);

    cudaFuncSetAttribute((const void*)gemm_f16<1>,
                         cudaFuncAttributeMaxDynamicSharedMemorySize, SMEM_TOTAL);
    cudaFuncSetAttribute((const void*)gemm_f16<2>,
                         cudaFuncAttributeMaxDynamicSharedMemorySize, SMEM_TOTAL);
    cudaFuncSetAttribute((const void*)gemm3_mma,
                         cudaFuncAttributeMaxDynamicSharedMemorySize, G3_SMEM);

    prep_kernel<<<(RTOT + 255) / 256, 256>>>(p1_w, p2_w, W_w, pi, W_b,
                                             w1, w2, wpi, bpi, a1);
    ema_fused_kernel<<<B_SZ * 64, 256>>>(seq, beta_raw, a1);

    // GEMM1: hid = relu(A1 @ p1_w^T + p1_b) -> fp16  (fp32 acc)
    {
        dim3 grid(N1 / BN, M_PAD / BM);
        gemm_f16<1><<<grid, 128, SMEM_TOTAL>>>(a1, w1, p1_b, hid, nullptr, N1, K1);
    }
    // GEMM2: x_hat = hid @ p2_w^T + p2_b -> fp32 d_out + fp16 scratch
    {
        dim3 grid(N2 / BN, M_PAD / BM);
        gemm_f16<2><<<grid, 128, SMEM_TOTAL>>>(hid, w2, p2_b, xh16, xhat, N2, K2);
    }
    // GEMM3: logits = xh16 @ Wpi^T + bpi
    gemm3_mma<<<M_PAD / BM, 256, G3_SMEM>>>(xh16, wpi, bpi, logits);
}

// round 15
// speedup vs baseline: 1.2514x; 1.2514x over previous
#include <cuda_runtime.h>
#include <cuda_fp16.h>
#include <math.h>
#include <stdint.h>

// ---------------------------------------------------------------------------
// Problem constants
// ---------------------------------------------------------------------------
#define B_SZ 16
#define T_SZ 1024
#define D_SZ 1024
#define E_SZ 64
#define TS   (T_SZ - 1)          // 1023
#define M_ROWS (TS * B_SZ)       // 16368
#define M_PAD  16384
#define K1 2048
#define N1 4096
#define K2 4096
#define N2 1024
#define K3 1024
#define N3 64
#define LOGITS_ELEMS (M_ROWS * E_SZ)

// Big-GEMM tiling: block 128x128, 4 warps (2x2), warp tile 64x64, BK=32
#define BM 128
#define BN 128
#define BK 32
#define STAGES 5
#define ROW_BYTES 80             // 64B data + 16B skew
#define ARR_BYTES (BM * ROW_BYTES)          // 10240
#define STAGE_BYTES (2 * ARR_BYTES)         // 20480
#define SMEM_TOTAL (STAGES * STAGE_BYTES)   // 102400 (x2 CTAs = 200KB < 228KB)

// GEMM3 tiling (256 threads, 8 warps 4x2, warp tile 32x32)
#define G3_ROW 80
#define G3_A_BYTES (BM * G3_ROW)
#define G3_B_BYTES (64 * G3_ROW)
#define G3_STAGE (G3_A_BYTES + G3_B_BYTES)
#define G3_SMEM (4 * G3_STAGE)

// ---------------------------------------------------------------------------
// Device scratch
// ---------------------------------------------------------------------------
__device__ __align__(16) __half g_a1[(size_t)M_PAD * K1];
__device__ __align__(16) __half g_w1[(size_t)N1 * K1];
__device__ __align__(16) __half g_hid[(size_t)M_PAD * N1];
__device__ __align__(16) __half g_w2[(size_t)N2 * K2];
__device__ __align__(16) __half g_xh16[(size_t)M_PAD * N2];
__device__ __align__(16) __half g_wpi[(size_t)N3 * K3];
__device__ __align__(16) float  g_bpi[N3];

// ---------------------------------------------------------------------------
// PTX helpers
// ---------------------------------------------------------------------------
__device__ __forceinline__ uint32_t smem_u32(const void* p) {
    uint32_t a;
    asm("{ .reg .u64 t; cvta.to.shared.u64 t, %1; cvt.u32.u64 %0, t; }" : "=r"(a) : "l"(p));
    return a;
}
__device__ __forceinline__ void cp_async16(uint32_t dst, const void* src) {
    asm volatile("cp.async.cg.shared.global [%0], [%1], 16;" :: "r"(dst), "l"(src));
}
__device__ __forceinline__ void cp_commit() {
    asm volatile("cp.async.commit_group;" ::: "memory");
}
template <int N>
__device__ __forceinline__ void cp_wait() {
    asm volatile("cp.async.wait_group %0;" :: "n"(N) : "memory");
}
__device__ __forceinline__ void ldsm_x4(uint32_t* r, uint32_t addr) {
    asm volatile("ldmatrix.sync.aligned.m8n8.x4.shared.b16 {%0,%1,%2,%3}, [%4];"
                 : "=r"(r[0]), "=r"(r[1]), "=r"(r[2]), "=r"(r[3]) : "r"(addr));
}
__device__ __forceinline__ void mma_f16(float* d, const uint32_t* a, uint32_t b0, uint32_t b1) {
    asm volatile(
        "mma.sync.aligned.m16n8k16.row.col.f32.f16.f16.f32 "
        "{%0,%1,%2,%3}, {%4,%5,%6,%7}, {%8,%9}, {%0,%1,%2,%3};"
        : "+f"(d[0]), "+f"(d[1]), "+f"(d[2]), "+f"(d[3])
        : "r"(a[0]), "r"(a[1]), "r"(a[2]), "r"(a[3]), "r"(b0), "r"(b1));
}
__device__ __forceinline__ ushort4 cvt4(float4 v) {
    return make_ushort4(
        __half_as_ushort(__float2half_rn(v.x)), __half_as_ushort(__float2half_rn(v.y)),
        __half_as_ushort(__float2half_rn(v.z)), __half_as_ushort(__float2half_rn(v.w)));
}

// ---------------------------------------------------------------------------
// Merged prep
// ---------------------------------------------------------------------------
#define R1 (N1 * K1 / 4)
#define R2 (N2 * K2 / 4)
#define R3 (N3 * K3 / 4)
#define RPAD ((M_PAD - M_ROWS) * K1 / 8)
#define RTOT (R1 + R2 + R3 + RPAD + N3)

__global__ void prep_kernel(const float* __restrict__ p1_w, const float* __restrict__ p2_w,
                            const float* __restrict__ W_w, const float* __restrict__ pi,
                            const float* __restrict__ Wb,
                            __half* __restrict__ w1, __half* __restrict__ w2,
                            __half* __restrict__ wpi, float* __restrict__ bpi,
                            __half* __restrict__ a1) {
    int i = blockIdx.x * blockDim.x + threadIdx.x;
    if (i < R1) {
        ((ushort4*)w1)[i] = cvt4(((const float4*)p1_w)[i]);
    } else if (i < R1 + R2) {
        int j = i - R1;
        ((ushort4*)w2)[j] = cvt4(((const float4*)p2_w)[j]);
    } else if (i < R1 + R2 + R3) {
        int j = i - R1 - R2;
        float4 v = ((const float4*)W_w)[j];
        float p = pi[j >> 8];
        v.x *= p; v.y *= p; v.z *= p; v.w *= p;
        ((ushort4*)wpi)[j] = cvt4(v);
    } else if (i < R1 + R2 + R3 + RPAD) {
        int j = i - R1 - R2 - R3;
        ((uint4*)(a1 + (size_t)M_ROWS * K1))[j] = make_uint4(0, 0, 0, 0);
    } else if (i < RTOT) {
        int j = i - R1 - R2 - R3 - RPAD;
        bpi[j] = Wb[j] * pi[j];
    }
}

// ---------------------------------------------------------------------------
// Fused EMA (chunked parallel scan) + x-half conversion
// ---------------------------------------------------------------------------
__global__ void __launch_bounds__(256)
ema_fused_kernel(const float* __restrict__ seq, const float* __restrict__ beta_raw,
                 __half* __restrict__ a1) {
    __shared__ float sL[16][16];
    __shared__ float sBP[16][16];
    const int tid = threadIdx.x;
    const int dl = tid & 15;
    const int c = tid >> 4;
    const int b = blockIdx.x >> 6;
    const int d = ((blockIdx.x & 63) << 4) + dl;
    const float beta = 1.0f / (1.0f + expf(-beta_raw[d]));
    const int t0 = c * 64;
    const int t1 = (t0 + 64 < TS) ? t0 + 64 : TS;
    const float* sp = seq + (size_t)b * T_SZ * D_SZ + d;

    float L = 0.0f, bp = 1.0f;
#pragma unroll 4
    for (int t = t0; t < t1; ++t) {
        L = fmaf(beta, L, sp[(size_t)t * D_SZ]);
        bp *= beta;
    }
    sL[c][dl] = L;
    sBP[c][dl] = bp;
    __syncthreads();

    float H = 0.0f;
    for (int j = 0; j < c; ++j)
        H = fmaf(sBP[j][dl], H, sL[j][dl]);

    float h = H;
#pragma unroll 4
    for (int t = t0; t < t1; ++t) {
        float x = sp[(size_t)t * D_SZ];
        h = fmaf(beta, h, x);
        const size_t m = (size_t)t * B_SZ + b;
        a1[m * K1 + d] = __float2half_rn(x);
        a1[m * K1 + D_SZ + d] = __float2half_rn(h);
    }
}

// ---------------------------------------------------------------------------
// fp16 mma.sync GEMM, fp32 acc, warp tile 64x64, 128 threads (4 warps 2x2),
// BK=32, 5-stage cp.async + register double-buffered fragments (R11 form).
// EPI 1: relu(acc+bias) -> fp16 outH
// EPI 2: acc+bias -> fp16 outH (all rows) + fp32 outF (m<M_ROWS)
// ---------------------------------------------------------------------------
template <int EPI>
__global__ void __launch_bounds__(128, 2)
gemm_f16(const __half* __restrict__ A, const __half* __restrict__ Wh,
         const float* __restrict__ bias,
         __half* __restrict__ outH, float* __restrict__ outF, int N, int K) {
    extern __shared__ char smem[];
    const uint32_t sbase = smem_u32(smem);
    const int tid = threadIdx.x;
    const int lane = tid & 31;
    const int wid = tid >> 5;            // 0..3
    const int wm0 = (wid & 1) * 64;
    const int wn0 = (wid >> 1) * 64;
    const int m0 = blockIdx.y * BM;
    const int n0 = blockIdx.x * BN;
    const int NK = K / BK;

    float acc[4][8][4];
#pragma unroll
    for (int a = 0; a < 4; ++a)
#pragma unroll
        for (int b = 0; b < 8; ++b)
#pragma unroll
            for (int c = 0; c < 4; ++c) acc[a][b][c] = 0.0f;

    // double-buffered fragments
    uint32_t ah[2][4][4], bh[2][4][4];

    auto load_stage = [&](int kc) {
        const uint32_t sb = sbase + (uint32_t)(kc % STAGES) * STAGE_BYTES;
        const size_t gcol = (size_t)kc * BK;
#pragma unroll
        for (int q = 0; q < 4; ++q) {
            const int s = tid + q * 128;
            const int r = s >> 2, ch = s & 3;
            const uint32_t so = (uint32_t)(r * ROW_BYTES + ch * 16);
            cp_async16(sb + so, A + (size_t)(m0 + r) * K + gcol + ch * 8);
            cp_async16(sb + ARR_BYTES + so, Wh + (size_t)(n0 + r) * K + gcol + ch * 8);
        }
        cp_commit();
    };

    const uint32_t lrow = (uint32_t)(lane & 15);
    const uint32_t lcol = (uint32_t)((lane >> 4) * 16);

    auto ldsm_frags = [&](int kc, int j, uint32_t (*A4)[4], uint32_t (*B4)[4]) {
        const uint32_t sb = sbase + (uint32_t)(kc % STAGES) * STAGE_BYTES;
        const uint32_t colb = (uint32_t)(j * 32) + lcol;
#pragma unroll
        for (int mf = 0; mf < 4; ++mf)
            ldsm_x4(A4[mf], sb + (uint32_t)((wm0 + mf * 16 + lrow) * ROW_BYTES) + colb);
#pragma unroll
        for (int np = 0; np < 4; ++np)
            ldsm_x4(B4[np], sb + ARR_BYTES +
                            (uint32_t)((wn0 + np * 16 + lrow) * ROW_BYTES) + colb);
    };

    auto mma_all = [&](uint32_t (*A4)[4], uint32_t (*B4)[4]) {
#pragma unroll
        for (int mf = 0; mf < 4; ++mf) {
#pragma unroll
            for (int np = 0; np < 4; ++np) {
                mma_f16(acc[mf][2 * np],     A4[mf], B4[np][0], B4[np][2]);
                mma_f16(acc[mf][2 * np + 1], A4[mf], B4[np][1], B4[np][3]);
            }
        }
    };

    // Prologue: 4 stages in flight; stage 0 resident; frags (0, j0) loaded.
    load_stage(0);
    load_stage(1);
    load_stage(2);
    load_stage(3);
    cp_wait<3>();
    __syncthreads();
    ldsm_frags(0, 0, ah[0], bh[0]);

    for (int kc = 0; kc < NK; ++kc) {
        // j = 0: prefetch frags (kc, j1) into buf1, compute buf0
        ldsm_frags(kc, 1, ah[1], bh[1]);
        mma_all(ah[0], bh[0]);

        // j = 1: advance stage pipeline, prefetch frags (kc+1, j0) into buf0
        if (kc + 1 < NK) {
            if (kc + 4 < NK) {
                load_stage(kc + 4);   // slot of kc-1: reads complete before prior barrier
                cp_wait<3>();         // retires group kc+1 (stage kc+1 resident)
            } else if (kc + 3 < NK) {
                cp_wait<2>();
            } else if (kc + 2 < NK) {
                cp_wait<1>();
            } else {
                cp_wait<0>();
            }
            __syncthreads();
            ldsm_frags(kc + 1, 0, ah[0], bh[0]);
        }
        mma_all(ah[1], bh[1]);
    }

    // Epilogue
    const int g = lane >> 2;
    const int t2 = (lane & 3) * 2;
#pragma unroll
    for (int mf = 0; mf < 4; ++mf) {
#pragma unroll
        for (int nf = 0; nf < 8; ++nf) {
            const int n = n0 + wn0 + nf * 8 + t2;
            const float2 bv = *(const float2*)(bias + n);
#pragma unroll
            for (int h = 0; h < 2; ++h) {
                const int m = m0 + wm0 + mf * 16 + g + h * 8;
                float v0 = acc[mf][nf][h * 2 + 0] + bv.x;
                float v1 = acc[mf][nf][h * 2 + 1] + bv.y;
                if (EPI == 1) {
                    v0 = fmaxf(v0, 0.0f);
                    v1 = fmaxf(v1, 0.0f);
                    *(ushort2*)(outH + (size_t)m * N + n) =
                        make_ushort2(__half_as_ushort(__float2half_rn(v0)),
                                     __half_as_ushort(__float2half_rn(v1)));
                } else {
                    *(ushort2*)(outH + (size_t)m * N + n) =
                        make_ushort2(__half_as_ushort(__float2half_rn(v0)),
                                     __half_as_ushort(__float2half_rn(v1)));
                    if (m < M_ROWS)
                        *(float2*)(outF + (size_t)m * N + n) = make_float2(v0, v1);
                }
            }
        }
    }
}

// ---------------------------------------------------------------------------
// GEMM3 (mma fp16): logits = xh16 @ Wpi^T + bpi   (BK=32, 4 stages)
// ---------------------------------------------------------------------------
__global__ void __launch_bounds__(256, 1)
gemm3_mma(const __half* __restrict__ A, const __half* __restrict__ Wpi,
          const float* __restrict__ bpi, float* __restrict__ C) {
    const int K = K3;
    extern __shared__ char smem[];
    const uint32_t sbase = smem_u32(smem);
    const int tid = threadIdx.x;
    const int lane = tid & 31;
    const int wid = tid >> 5;
    const int wm0 = (wid & 3) * 32;
    const int wn0 = (wid >> 2) * 32;
    const int m0 = blockIdx.x * BM;
    const int NK = K / 32;

    float acc[2][4][4];
#pragma unroll
    for (int a = 0; a < 2; ++a)
#pragma unroll
        for (int b = 0; b < 4; ++b)
#pragma unroll
            for (int c = 0; c < 4; ++c) acc[a][b][c] = 0.0f;

    auto load_stage = [&](int kc) {
        const uint32_t sb = sbase + (uint32_t)(kc % 4) * G3_STAGE;
        const size_t gcol = (size_t)kc * 32;
#pragma unroll
        for (int q = 0; q < 2; ++q) {
            const int s = tid + q * 256;
            const int r = s >> 2, ch = s & 3;
            cp_async16(sb + (uint32_t)(r * G3_ROW + ch * 16),
                       A + (size_t)(m0 + r) * K + gcol + ch * 8);
        }
        {
            const int r = tid >> 2, ch = tid & 3;
            cp_async16(sb + G3_A_BYTES + (uint32_t)(r * G3_ROW + ch * 16),
                       Wpi + (size_t)r * K + gcol + ch * 8);
        }
        cp_commit();
    };

    load_stage(0);
    load_stage(1);
    load_stage(2);

    const uint32_t lrow = (uint32_t)(lane & 15);
    const uint32_t lcol = (uint32_t)((lane >> 4) * 16);

    for (int kc = 0; kc < NK; ++kc) {
        const int rem = NK - 1 - kc;
        if (rem >= 2) cp_wait<2>();
        else if (rem == 1) cp_wait<1>();
        else cp_wait<0>();
        __syncthreads();
        if (kc + 3 < NK) load_stage(kc + 3);

        const uint32_t sb = sbase + (uint32_t)(kc % 4) * G3_STAGE;
#pragma unroll
        for (int j = 0; j < 2; ++j) {
            const uint32_t colb = (uint32_t)(j * 32) + lcol;
            uint32_t ah[2][4];
#pragma unroll
            for (int mf = 0; mf < 2; ++mf)
                ldsm_x4(ah[mf], sb + (uint32_t)((wm0 + mf * 16 + lrow) * G3_ROW) + colb);
            uint32_t bh[2][4];
#pragma unroll
            for (int np = 0; np < 2; ++np)
                ldsm_x4(bh[np], sb + G3_A_BYTES +
                                (uint32_t)((wn0 + np * 16 + lrow) * G3_ROW) + colb);
#pragma unroll
            for (int mf = 0; mf < 2; ++mf) {
#pragma unroll
                for (int np = 0; np < 2; ++np) {
                    mma_f16(acc[mf][2 * np],     ah[mf], bh[np][0], bh[np][2]);
                    mma_f16(acc[mf][2 * np + 1], ah[mf], bh[np][1], bh[np][3]);
                }
            }
        }
    }

    const int g = lane >> 2;
    const int t2 = (lane & 3) * 2;
#pragma unroll
    for (int mf = 0; mf < 2; ++mf) {
#pragma unroll
        for (int nf = 0; nf < 4; ++nf) {
            const int n = wn0 + nf * 8 + t2;
            const float2 bv = *(const float2*)(bpi + n);
#pragma unroll
            for (int h = 0; h < 2; ++h) {
                const int m = m0 + wm0 + mf * 16 + g + h * 8;
                if (m < M_ROWS) {
                    float v0 = acc[mf][nf][h * 2 + 0] + bv.x;
                    float v1 = acc[mf][nf][h * 2 + 1] + bv.y;
                    *(float2*)(C + (size_t)m * N3 + n) = make_float2(v0, v1);
                }
            }
        }
    }
}

// ---------------------------------------------------------------------------
// Launch
// ---------------------------------------------------------------------------
extern "C" void kernel_launch(void* const* d_in, const int* in_sizes, int n_in,
                              void* d_out, int out_size) {
    const float* seq      = (const float*)d_in[0];
    const float* pi       = (const float*)d_in[1];
    const float* beta_raw = (const float*)d_in[2];
    const float* p1_w     = (const float*)d_in[3];
    const float* p1_b     = (const float*)d_in[4];
    const float* p2_w     = (const float*)d_in[5];
    const float* p2_b     = (const float*)d_in[6];
    const float* W_w      = (const float*)d_in[7];
    const float* W_b      = (const float*)d_in[8];

    float* logits = (float*)d_out;
    float* xhat   = (float*)d_out + LOGITS_ELEMS;

    __half *a1, *w1, *hid, *w2, *xh16, *wpi;
    float* bpi;
    cudaGetSymbolAddress((void**)&a1, g_a1);
    cudaGetSymbolAddress((void**)&w1, g_w1);
    cudaGetSymbolAddress((void**)&hid, g_hid);
    cudaGetSymbolAddress((void**)&w2, g_w2);
    cudaGetSymbolAddress((void**)&xh16, g_xh16);
    cudaGetSymbolAddress((void**)&wpi, g_wpi);
    cudaGetSymbolAddress((void**)&bpi, g_bpi);

    cudaFuncSetAttribute((const void*)gemm_f16<1>,
                         cudaFuncAttributeMaxDynamicSharedMemorySize, SMEM_TOTAL);
    cudaFuncSetAttribute((const void*)gemm_f16<2>,
                         cudaFuncAttributeMaxDynamicSharedMemorySize, SMEM_TOTAL);
    cudaFuncSetAttribute((const void*)gemm3_mma,
                         cudaFuncAttributeMaxDynamicSharedMemorySize, G3_SMEM);

    prep_kernel<<<(RTOT + 255) / 256, 256>>>(p1_w, p2_w, W_w, pi, W_b,
                                             w1, w2, wpi, bpi, a1);
    ema_fused_kernel<<<B_SZ * 64, 256>>>(seq, beta_raw, a1);

    // GEMM1: hid = relu(A1 @ p1_w^T + p1_b) -> fp16  (fp32 acc)
    {
        dim3 grid(N1 / BN, M_PAD / BM);
        gemm_f16<1><<<grid, 128, SMEM_TOTAL>>>(a1, w1, p1_b, hid, nullptr, N1, K1);
    }
    // GEMM2: x_hat = hid @ p2_w^T + p2_b -> fp32 d_out + fp16 scratch
    {
        dim3 grid(N2 / BN, M_PAD / BM);
        gemm_f16<2><<<grid, 128, SMEM_TOTAL>>>(hid, w2, p2_b, xh16, xhat, N2, K2);
    }
    // GEMM3: logits = xh16 @ Wpi^T + bpi
    gemm3_mma<<<M_PAD / BM, 256, G3_SMEM>>>(xh16, wpi, bpi, logits);
}

// round 16
// speedup vs baseline: 1.2564x; 1.0040x over previous
#include <cuda_runtime.h>
#include <cuda_fp16.h>
#include <math.h>
#include <stdint.h>

// ---------------------------------------------------------------------------
// Problem constants
// ---------------------------------------------------------------------------
#define B_SZ 16
#define T_SZ 1024
#define D_SZ 1024
#define E_SZ 64
#define TS   (T_SZ - 1)          // 1023
#define M_ROWS (TS * B_SZ)       // 16368
#define M_PAD  16384
#define K1 2048
#define N1 4096
#define K2 4096
#define N2 1024
#define K3 1024
#define N3 64
#define LOGITS_ELEMS (M_ROWS * E_SZ)

// Big-GEMM tiling: block 128x128, 4 warps (2x2), warp tile 64x64, BK=32
#define BM 128
#define BN 128
#define BK 32
#define STAGES 5
#define ROW_BYTES 80             // 64B data + 16B skew
#define ARR_BYTES (BM * ROW_BYTES)          // 10240
#define STAGE_BYTES (2 * ARR_BYTES)         // 20480
#define SMEM_TOTAL (STAGES * STAGE_BYTES)   // 102400 (x2 CTAs = 200KB < 228KB)

// GEMM3 tiling (256 threads, 8 warps 4x2, warp tile 32x32)
#define G3_ROW 80
#define G3_A_BYTES (BM * G3_ROW)
#define G3_B_BYTES (64 * G3_ROW)
#define G3_STAGE (G3_A_BYTES + G3_B_BYTES)
#define G3_SMEM (4 * G3_STAGE)

// ---------------------------------------------------------------------------
// Device scratch
// ---------------------------------------------------------------------------
__device__ __align__(16) __half g_a1[(size_t)M_PAD * K1];
__device__ __align__(16) __half g_w1[(size_t)N1 * K1];
__device__ __align__(16) __half g_hid[(size_t)M_PAD * N1];
__device__ __align__(16) __half g_w2[(size_t)N2 * K2];
__device__ __align__(16) __half g_xh16[(size_t)M_PAD * N2];
__device__ __align__(16) __half g_wpi[(size_t)N3 * K3];
__device__ __align__(16) float  g_bpi[N3];

// ---------------------------------------------------------------------------
// PTX helpers
// ---------------------------------------------------------------------------
__device__ __forceinline__ uint32_t smem_u32(const void* p) {
    uint32_t a;
    asm("{ .reg .u64 t; cvta.to.shared.u64 t, %1; cvt.u32.u64 %0, t; }" : "=r"(a) : "l"(p));
    return a;
}
__device__ __forceinline__ void cp_async16(uint32_t dst, const void* src) {
    asm volatile("cp.async.cg.shared.global [%0], [%1], 16;" :: "r"(dst), "l"(src));
}
__device__ __forceinline__ void cp_commit() {
    asm volatile("cp.async.commit_group;" ::: "memory");
}
template <int N>
__device__ __forceinline__ void cp_wait() {
    asm volatile("cp.async.wait_group %0;" :: "n"(N) : "memory");
}
__device__ __forceinline__ void ldsm_x4(uint32_t* r, uint32_t addr) {
    asm volatile("ldmatrix.sync.aligned.m8n8.x4.shared.b16 {%0,%1,%2,%3}, [%4];"
                 : "=r"(r[0]), "=r"(r[1]), "=r"(r[2]), "=r"(r[3]) : "r"(addr));
}
__device__ __forceinline__ void mma_f16(float* d, const uint32_t* a, uint32_t b0, uint32_t b1) {
    asm volatile(
        "mma.sync.aligned.m16n8k16.row.col.f32.f16.f16.f32 "
        "{%0,%1,%2,%3}, {%4,%5,%6,%7}, {%8,%9}, {%0,%1,%2,%3};"
        : "+f"(d[0]), "+f"(d[1]), "+f"(d[2]), "+f"(d[3])
        : "r"(a[0]), "r"(a[1]), "r"(a[2]), "r"(a[3]), "r"(b0), "r"(b1));
}
__device__ __forceinline__ ushort4 cvt4(float4 v) {
    return make_ushort4(
        __half_as_ushort(__float2half_rn(v.x)), __half_as_ushort(__float2half_rn(v.y)),
        __half_as_ushort(__float2half_rn(v.z)), __half_as_ushort(__float2half_rn(v.w)));
}

// ---------------------------------------------------------------------------
// Merged prep
// ---------------------------------------------------------------------------
#define R1 (N1 * K1 / 4)
#define R2 (N2 * K2 / 4)
#define R3 (N3 * K3 / 4)
#define RPAD ((M_PAD - M_ROWS) * K1 / 8)
#define RTOT (R1 + R2 + R3 + RPAD + N3)

__global__ void prep_kernel(const float* __restrict__ p1_w, const float* __restrict__ p2_w,
                            const float* __restrict__ W_w, const float* __restrict__ pi,
                            const float* __restrict__ Wb,
                            __half* __restrict__ w1, __half* __restrict__ w2,
                            __half* __restrict__ wpi, float* __restrict__ bpi,
                            __half* __restrict__ a1) {
    int i = blockIdx.x * blockDim.x + threadIdx.x;
    if (i < R1) {
        ((ushort4*)w1)[i] = cvt4(((const float4*)p1_w)[i]);
    } else if (i < R1 + R2) {
        int j = i - R1;
        ((ushort4*)w2)[j] = cvt4(((const float4*)p2_w)[j]);
    } else if (i < R1 + R2 + R3) {
        int j = i - R1 - R2;
        float4 v = ((const float4*)W_w)[j];
        float p = pi[j >> 8];
        v.x *= p; v.y *= p; v.z *= p; v.w *= p;
        ((ushort4*)wpi)[j] = cvt4(v);
    } else if (i < R1 + R2 + R3 + RPAD) {
        int j = i - R1 - R2 - R3;
        ((uint4*)(a1 + (size_t)M_ROWS * K1))[j] = make_uint4(0, 0, 0, 0);
    } else if (i < RTOT) {
        int j = i - R1 - R2 - R3 - RPAD;
        bpi[j] = Wb[j] * pi[j];
    }
}

// ---------------------------------------------------------------------------
// Fused EMA (chunked parallel scan) + x-half conversion
// ---------------------------------------------------------------------------
__global__ void __launch_bounds__(256)
ema_fused_kernel(const float* __restrict__ seq, const float* __restrict__ beta_raw,
                 __half* __restrict__ a1) {
    __shared__ float sL[16][16];
    __shared__ float sBP[16][16];
    const int tid = threadIdx.x;
    const int dl = tid & 15;
    const int c = tid >> 4;
    const int b = blockIdx.x >> 6;
    const int d = ((blockIdx.x & 63) << 4) + dl;
    const float beta = 1.0f / (1.0f + expf(-beta_raw[d]));
    const int t0 = c * 64;
    const int t1 = (t0 + 64 < TS) ? t0 + 64 : TS;
    const float* sp = seq + (size_t)b * T_SZ * D_SZ + d;

    float L = 0.0f, bp = 1.0f;
#pragma unroll 4
    for (int t = t0; t < t1; ++t) {
        L = fmaf(beta, L, sp[(size_t)t * D_SZ]);
        bp *= beta;
    }
    sL[c][dl] = L;
    sBP[c][dl] = bp;
    __syncthreads();

    float H = 0.0f;
    for (int j = 0; j < c; ++j)
        H = fmaf(sBP[j][dl], H, sL[j][dl]);

    float h = H;
#pragma unroll 4
    for (int t = t0; t < t1; ++t) {
        float x = sp[(size_t)t * D_SZ];
        h = fmaf(beta, h, x);
        const size_t m = (size_t)t * B_SZ + b;
        a1[m * K1 + d] = __float2half_rn(x);
        a1[m * K1 + D_SZ + d] = __float2half_rn(h);
    }
}

// ---------------------------------------------------------------------------
// fp16 mma.sync GEMM, fp32 acc, warp tile 64x64, 128 threads (4 warps 2x2),
// BK=32, 5-stage cp.async + register double-buffered fragments (R11 form).
// EPI 1: relu(acc+bias) -> fp16 outH
// EPI 2: acc+bias -> fp16 outH (all rows) + fp32 outF (m<M_ROWS)
// ---------------------------------------------------------------------------
template <int EPI>
__global__ void __launch_bounds__(128, 2)
gemm_f16(const __half* __restrict__ A, const __half* __restrict__ Wh,
         const float* __restrict__ bias,
         __half* __restrict__ outH, float* __restrict__ outF, int N, int K) {
    extern __shared__ char smem[];
    const uint32_t sbase = smem_u32(smem);
    const int tid = threadIdx.x;
    const int lane = tid & 31;
    const int wid = tid >> 5;            // 0..3
    const int wm0 = (wid & 1) * 64;
    const int wn0 = (wid >> 1) * 64;
    const int m0 = blockIdx.y * BM;
    const int n0 = blockIdx.x * BN;
    const int NK = K / BK;

    float acc[4][8][4];
#pragma unroll
    for (int a = 0; a < 4; ++a)
#pragma unroll
        for (int b = 0; b < 8; ++b)
#pragma unroll
            for (int c = 0; c < 4; ++c) acc[a][b][c] = 0.0f;

    // double-buffered fragments
    uint32_t ah[2][4][4], bh[2][4][4];

    auto load_stage = [&](int kc) {
        const uint32_t sb = sbase + (uint32_t)(kc % STAGES) * STAGE_BYTES;
        const size_t gcol = (size_t)kc * BK;
#pragma unroll
        for (int q = 0; q < 4; ++q) {
            const int s = tid + q * 128;
            const int r = s >> 2, ch = s & 3;
            const uint32_t so = (uint32_t)(r * ROW_BYTES + ch * 16);
            cp_async16(sb + so, A + (size_t)(m0 + r) * K + gcol + ch * 8);
            cp_async16(sb + ARR_BYTES + so, Wh + (size_t)(n0 + r) * K + gcol + ch * 8);
        }
        cp_commit();
    };

    const uint32_t lrow = (uint32_t)(lane & 15);
    const uint32_t lcol = (uint32_t)((lane >> 4) * 16);

    auto ldsm_frags = [&](int kc, int j, uint32_t (*A4)[4], uint32_t (*B4)[4]) {
        const uint32_t sb = sbase + (uint32_t)(kc % STAGES) * STAGE_BYTES;
        const uint32_t colb = (uint32_t)(j * 32) + lcol;
#pragma unroll
        for (int mf = 0; mf < 4; ++mf)
            ldsm_x4(A4[mf], sb + (uint32_t)((wm0 + mf * 16 + lrow) * ROW_BYTES) + colb);
#pragma unroll
        for (int np = 0; np < 4; ++np)
            ldsm_x4(B4[np], sb + ARR_BYTES +
                            (uint32_t)((wn0 + np * 16 + lrow) * ROW_BYTES) + colb);
    };

    auto mma_all = [&](uint32_t (*A4)[4], uint32_t (*B4)[4]) {
#pragma unroll
        for (int mf = 0; mf < 4; ++mf) {
#pragma unroll
            for (int np = 0; np < 4; ++np) {
                mma_f16(acc[mf][2 * np],     A4[mf], B4[np][0], B4[np][2]);
                mma_f16(acc[mf][2 * np + 1], A4[mf], B4[np][1], B4[np][3]);
            }
        }
    };

    // Prologue: 4 stages in flight; stage 0 resident; frags (0, j0) loaded.
    load_stage(0);
    load_stage(1);
    load_stage(2);
    load_stage(3);
    cp_wait<3>();
    __syncthreads();
    ldsm_frags(0, 0, ah[0], bh[0]);

    for (int kc = 0; kc < NK; ++kc) {
        // j = 0: prefetch frags (kc, j1) into buf1, compute buf0
        ldsm_frags(kc, 1, ah[1], bh[1]);
        mma_all(ah[0], bh[0]);

        // j = 1: advance stage pipeline, prefetch frags (kc+1, j0) into buf0
        if (kc + 1 < NK) {
            if (kc + 4 < NK) {
                load_stage(kc + 4);   // slot of kc-1: reads complete before prior barrier
                cp_wait<3>();         // retires group kc+1 (stage kc+1 resident)
            } else if (kc + 3 < NK) {
                cp_wait<2>();
            } else if (kc + 2 < NK) {
                cp_wait<1>();
            } else {
                cp_wait<0>();
            }
            __syncthreads();
            ldsm_frags(kc + 1, 0, ah[0], bh[0]);
        }
        mma_all(ah[1], bh[1]);
    }

    // Epilogue
    const int g = lane >> 2;
    const int t2 = (lane & 3) * 2;
#pragma unroll
    for (int mf = 0; mf < 4; ++mf) {
#pragma unroll
        for (int nf = 0; nf < 8; ++nf) {
            const int n = n0 + wn0 + nf * 8 + t2;
            const float2 bv = *(const float2*)(bias + n);
#pragma unroll
            for (int h = 0; h < 2; ++h) {
                const int m = m0 + wm0 + mf * 16 + g + h * 8;
                float v0 = acc[mf][nf][h * 2 + 0] + bv.x;
                float v1 = acc[mf][nf][h * 2 + 1] + bv.y;
                if (EPI == 1) {
                    v0 = fmaxf(v0, 0.0f);
                    v1 = fmaxf(v1, 0.0f);
                    *(ushort2*)(outH + (size_t)m * N + n) =
                        make_ushort2(__half_as_ushort(__float2half_rn(v0)),
                                     __half_as_ushort(__float2half_rn(v1)));
                } else {
                    *(ushort2*)(outH + (size_t)m * N + n) =
                        make_ushort2(__half_as_ushort(__float2half_rn(v0)),
                                     __half_as_ushort(__float2half_rn(v1)));
                    if (m < M_ROWS)
                        *(float2*)(outF + (size_t)m * N + n) = make_float2(v0, v1);
                }
            }
        }
    }
}

// ---------------------------------------------------------------------------
// GEMM3 (mma fp16): logits = xh16 @ Wpi^T + bpi   (BK=32, 4 stages)
// Now with register double-buffered fragments (R11 pattern).
// ---------------------------------------------------------------------------
__global__ void __launch_bounds__(256, 1)
gemm3_mma(const __half* __restrict__ A, const __half* __restrict__ Wpi,
          const float* __restrict__ bpi, float* __restrict__ C) {
    const int K = K3;
    extern __shared__ char smem[];
    const uint32_t sbase = smem_u32(smem);
    const int tid = threadIdx.x;
    const int lane = tid & 31;
    const int wid = tid >> 5;
    const int wm0 = (wid & 3) * 32;
    const int wn0 = (wid >> 2) * 32;
    const int m0 = blockIdx.x * BM;
    const int NK = K / 32;

    float acc[2][4][4];
#pragma unroll
    for (int a = 0; a < 2; ++a)
#pragma unroll
        for (int b = 0; b < 4; ++b)
#pragma unroll
            for (int c = 0; c < 4; ++c) acc[a][b][c] = 0.0f;

    uint32_t ah[2][2][4], bh[2][2][4];

    auto load_stage = [&](int kc) {
        const uint32_t sb = sbase + (uint32_t)(kc % 4) * G3_STAGE;
        const size_t gcol = (size_t)kc * 32;
#pragma unroll
        for (int q = 0; q < 2; ++q) {
            const int s = tid + q * 256;
            const int r = s >> 2, ch = s & 3;
            cp_async16(sb + (uint32_t)(r * G3_ROW + ch * 16),
                       A + (size_t)(m0 + r) * K + gcol + ch * 8);
        }
        {
            const int r = tid >> 2, ch = tid & 3;
            cp_async16(sb + G3_A_BYTES + (uint32_t)(r * G3_ROW + ch * 16),
                       Wpi + (size_t)r * K + gcol + ch * 8);
        }
        cp_commit();
    };

    const uint32_t lrow = (uint32_t)(lane & 15);
    const uint32_t lcol = (uint32_t)((lane >> 4) * 16);

    auto ldsm_frags = [&](int kc, int j, uint32_t (*A4)[4], uint32_t (*B4)[4]) {
        const uint32_t sb = sbase + (uint32_t)(kc % 4) * G3_STAGE;
        const uint32_t colb = (uint32_t)(j * 32) + lcol;
#pragma unroll
        for (int mf = 0; mf < 2; ++mf)
            ldsm_x4(A4[mf], sb + (uint32_t)((wm0 + mf * 16 + lrow) * G3_ROW) + colb);
#pragma unroll
        for (int np = 0; np < 2; ++np)
            ldsm_x4(B4[np], sb + G3_A_BYTES +
                            (uint32_t)((wn0 + np * 16 + lrow) * G3_ROW) + colb);
    };

    auto mma_all = [&](uint32_t (*A4)[4], uint32_t (*B4)[4]) {
#pragma unroll
        for (int mf = 0; mf < 2; ++mf) {
#pragma unroll
            for (int np = 0; np < 2; ++np) {
                mma_f16(acc[mf][2 * np],     A4[mf], B4[np][0], B4[np][2]);
                mma_f16(acc[mf][2 * np + 1], A4[mf], B4[np][1], B4[np][3]);
            }
        }
    };

    // Prologue: 3 stages in flight; stage 0 resident; frags (0, 0) loaded.
    load_stage(0);
    load_stage(1);
    load_stage(2);
    cp_wait<2>();
    __syncthreads();
    ldsm_frags(0, 0, ah[0], bh[0]);

    for (int kc = 0; kc < NK; ++kc) {
        // j = 0: prefetch frags (kc, 1) into buf1, compute buf0
        ldsm_frags(kc, 1, ah[1], bh[1]);
        mma_all(ah[0], bh[0]);
        // j = 1: advance stage pipeline, prefetch frags (kc+1, 0)
        if (kc + 1 < NK) {
            if (kc + 3 < NK) {
                load_stage(kc + 3);
                cp_wait<2>();
            } else if (kc + 2 < NK) {
                cp_wait<1>();
            } else {
                cp_wait<0>();
            }
            __syncthreads();
            ldsm_frags(kc + 1, 0, ah[0], bh[0]);
        }
        mma_all(ah[1], bh[1]);
    }

    const int g = lane >> 2;
    const int t2 = (lane & 3) * 2;
#pragma unroll
    for (int mf = 0; mf < 2; ++mf) {
#pragma unroll
        for (int nf = 0; nf < 4; ++nf) {
            const int n = wn0 + nf * 8 + t2;
            const float2 bv = *(const float2*)(bpi + n);
#pragma unroll
            for (int h = 0; h < 2; ++h) {
                const int m = m0 + wm0 + mf * 16 + g + h * 8;
                if (m < M_ROWS) {
                    float v0 = acc[mf][nf][h * 2 + 0] + bv.x;
                    float v1 = acc[mf][nf][h * 2 + 1] + bv.y;
                    *(float2*)(C + (size_t)m * N3 + n) = make_float2(v0, v1);
                }
            }
        }
    }
}

// ---------------------------------------------------------------------------
// Launch
// ---------------------------------------------------------------------------
extern "C" void kernel_launch(void* const* d_in, const int* in_sizes, int n_in,
                              void* d_out, int out_size) {
    const float* seq      = (const float*)d_in[0];
    const float* pi       = (const float*)d_in[1];
    const float* beta_raw = (const float*)d_in[2];
    const float* p1_w     = (const float*)d_in[3];
    const float* p1_b     = (const float*)d_in[4];
    const float* p2_w     = (const float*)d_in[5];
    const float* p2_b     = (const float*)d_in[6];
    const float* W_w      = (const float*)d_in[7];
    const float* W_b      = (const float*)d_in[8];

    float* logits = (float*)d_out;
    float* xhat   = (float*)d_out + LOGITS_ELEMS;

    __half *a1, *w1, *hid, *w2, *xh16, *wpi;
    float* bpi;
    cudaGetSymbolAddress((void**)&a1, g_a1);
    cudaGetSymbolAddress((void**)&w1, g_w1);
    cudaGetSymbolAddress((void**)&hid, g_hid);
    cudaGetSymbolAddress((void**)&w2, g_w2);
    cudaGetSymbolAddress((void**)&xh16, g_xh16);
    cudaGetSymbolAddress((void**)&wpi, g_wpi);
    cudaGetSymbolAddress((void**)&bpi, g_bpi);

    cudaFuncSetAttribute((const void*)gemm_f16<1>,
                         cudaFuncAttributeMaxDynamicSharedMemorySize, SMEM_TOTAL);
    cudaFuncSetAttribute((const void*)gemm_f16<2>,
                         cudaFuncAttributeMaxDynamicSharedMemorySize, SMEM_TOTAL);
    cudaFuncSetAttribute((const void*)gemm3_mma,
                         cudaFuncAttributeMaxDynamicSharedMemorySize, G3_SMEM);

    prep_kernel<<<(RTOT + 255) / 256, 256>>>(p1_w, p2_w, W_w, pi, W_b,
                                             w1, w2, wpi, bpi, a1);
    ema_fused_kernel<<<B_SZ * 64, 256>>>(seq, beta_raw, a1);

    // GEMM1: hid = relu(A1 @ p1_w^T + p1_b) -> fp16  (fp32 acc)
    {
        dim3 grid(N1 / BN, M_PAD / BM);
        gemm_f16<1><<<grid, 128, SMEM_TOTAL>>>(a1, w1, p1_b, hid, nullptr, N1, K1);
    }
    // GEMM2: x_hat = hid @ p2_w^T + p2_b -> fp32 d_out + fp16 scratch
    {
        dim3 grid(N2 / BN, M_PAD / BM);
        gemm_f16<2><<<grid, 128, SMEM_TOTAL>>>(hid, w2, p2_b, xh16, xhat, N2, K2);
    }
    // GEMM3: logits = xh16 @ Wpi^T + bpi
    gemm3_mma<<<M_PAD / BM, 256, G3_SMEM>>>(xh16, wpi, bpi, logits);
}